// round 1
// baseline (speedup 1.0000x reference)
#include <cuda_runtime.h>
#include <math.h>

// ---------------------------------------------------------------------------
// SpSpMM: C[n,n] = A @ B, A and B given as COO (indices [2,NNZ], values [NNZ]),
// duplicates sum. Output dense f32.
//
// Strategy: C = sum_k outer(A[:,k], B[k,:]). Bucket A entries by column,
// B entries by row, then per-k outer products scattered with float atomics.
// Expected pair count ~ N * degA * degB / N = 4096*32*32/... ≈ 4.2M MACs.
// ---------------------------------------------------------------------------

#define N_MAX 4096
#define CAP   256      // per-k bucket capacity (mean occupancy 32; overflow ~impossible)

__device__ int   g_cntA[N_MAX];
__device__ int   g_cntB[N_MAX];
__device__ int   g_rA[N_MAX * CAP];   // row index of A entry with column k
__device__ float g_vA[N_MAX * CAP];
__device__ int   g_cB[N_MAX * CAP];   // col index of B entry with row k
__device__ float g_vB[N_MAX * CAP];

// ---------------------------------------------------------------------------
// K1: zero output + counters
// ---------------------------------------------------------------------------
__global__ void zero_kernel(float* __restrict__ C, int total4, int n) {
    int idx    = blockIdx.x * blockDim.x + threadIdx.x;
    int stride = gridDim.x * blockDim.x;
    float4 z = make_float4(0.f, 0.f, 0.f, 0.f);
    float4* C4 = reinterpret_cast<float4*>(C);
    for (int i = idx; i < total4; i += stride) C4[i] = z;
    // counters (n <= total4 always here)
    for (int i = idx; i < n; i += stride) { g_cntA[i] = 0; g_cntB[i] = 0; }
}

// ---------------------------------------------------------------------------
// K2: bucket A by column.  a_idx layout: [2, nnz] row-major:
//     a_idx[t]        = row i
//     a_idx[nnz + t]  = col k
// ---------------------------------------------------------------------------
__global__ void build_a_kernel(const int* __restrict__ a_idx,
                               const float* __restrict__ a_val,
                               int nnz, int n) {
    int t = blockIdx.x * blockDim.x + threadIdx.x;
    if (t >= nnz) return;
    int i = a_idx[t];
    int k = a_idx[nnz + t];
    if ((unsigned)k >= (unsigned)n || (unsigned)k >= (unsigned)N_MAX) return;
    int slot = atomicAdd(&g_cntA[k], 1);
    if (slot < CAP) {
        g_rA[k * CAP + slot] = i;
        g_vA[k * CAP + slot] = a_val[t];
    }
}

// ---------------------------------------------------------------------------
// K3: bucket B by row.
//     b_idx[t]        = row k
//     b_idx[nnz + t]  = col j
// ---------------------------------------------------------------------------
__global__ void build_b_kernel(const int* __restrict__ b_idx,
                               const float* __restrict__ b_val,
                               int nnz, int n) {
    int t = blockIdx.x * blockDim.x + threadIdx.x;
    if (t >= nnz) return;
    int k = b_idx[t];
    int j = b_idx[nnz + t];
    if ((unsigned)k >= (unsigned)n || (unsigned)k >= (unsigned)N_MAX) return;
    int slot = atomicAdd(&g_cntB[k], 1);
    if (slot < CAP) {
        g_cB[k * CAP + slot] = j;
        g_vB[k * CAP + slot] = b_val[t];
    }
}

// ---------------------------------------------------------------------------
// K4: per-k outer product, scattered float atomics into C.
// One CTA per k.  blockDim = (32, 8).
// threadIdx.x strides the B list (contiguous j -> somewhat coalesced atomics
// within a warp when j's cluster), threadIdx.y strides the A list.
// ---------------------------------------------------------------------------
__global__ void product_kernel(float* __restrict__ C, int n) {
    int k  = blockIdx.x;
    if (k >= n) return;
    int cA = min(g_cntA[k], CAP);
    int cB = min(g_cntB[k], CAP);
    if (cA == 0 || cB == 0) return;

    __shared__ int   sR[CAP];
    __shared__ float sVA[CAP];
    __shared__ int   sC[CAP];
    __shared__ float sVB[CAP];

    int tid = threadIdx.y * 32 + threadIdx.x;
    for (int i = tid; i < cA; i += 256) { sR[i] = g_rA[k * CAP + i]; sVA[i] = g_vA[k * CAP + i]; }
    for (int i = tid; i < cB; i += 256) { sC[i] = g_cB[k * CAP + i]; sVB[i] = g_vB[k * CAP + i]; }
    __syncthreads();

    for (int ia = threadIdx.y; ia < cA; ia += 8) {
        float av = sVA[ia];
        long long rowbase = (long long)sR[ia] * n;
        for (int jb = threadIdx.x; jb < cB; jb += 32) {
            atomicAdd(&C[rowbase + sC[jb]], av * sVB[jb]);
        }
    }
}

// ---------------------------------------------------------------------------
// Host launcher (graph-capturable: kernel launches only)
// ---------------------------------------------------------------------------
extern "C" void kernel_launch(void* const* d_in, const int* in_sizes, int n_in,
                              void* d_out, int out_size) {
    const int*   a_idx = (const int*)  d_in[0];   // [2, NNZA]
    const float* a_val = (const float*)d_in[1];   // [NNZA]
    const int*   b_idx = (const int*)  d_in[2];   // [2, NNZB]
    const float* b_val = (const float*)d_in[3];   // [NNZB]
    float*       C     = (float*)d_out;

    int nnzA = in_sizes[1];
    int nnzB = in_sizes[3];
    int N    = (int)(sqrt((double)out_size) + 0.5);   // 4096

    // K1: zero output + counters
    {
        int total4 = out_size / 4;   // N*N divisible by 4
        zero_kernel<<<2048, 256>>>(C, total4, N);
    }

    // K2/K3: bucket A by column, B by row
    build_a_kernel<<<(nnzA + 255) / 256, 256>>>(a_idx, a_val, nnzA, N);
    build_b_kernel<<<(nnzB + 255) / 256, 256>>>(b_idx, b_val, nnzB, N);

    // K4: outer products
    {
        dim3 blk(32, 8);
        product_kernel<<<N, blk>>>(C, N);
    }
}

// round 2
// speedup vs baseline: 1.2396x; 1.2396x over previous
#include <cuda_runtime.h>
#include <math.h>

// ---------------------------------------------------------------------------
// SpSpMM: C[n,n] = A @ B, COO inputs (duplicates sum), dense f32 output.
//
// Row formulation: C[i,:] = sum over A-entries (i,k,av) of av * B[k,:].
// Bucket A by row i, B by row k. One CTA per output row accumulates the full
// 4096-wide row in SMEM (shared atomics), then streams it out coalesced.
// No global atomics, no separate zero pass for C.
// ---------------------------------------------------------------------------

#define N_MAX 4096
#define CAP   256      // per-bucket capacity (mean 32; Poisson tail @256 ~ 0)

__device__ int   g_cntA[N_MAX];          // entries of A in row i
__device__ int   g_cntB[N_MAX];          // entries of B in row k
__device__ int   g_kA[N_MAX * CAP];      // col k of A entry in row i
__device__ float g_vA[N_MAX * CAP];
__device__ int   g_cB[N_MAX * CAP];      // col j of B entry in row k
__device__ float g_vB[N_MAX * CAP];

// ---------------------------------------------------------------------------
// K1: zero counters (tiny)
// ---------------------------------------------------------------------------
__global__ void zero_counters(int n) {
    int i = blockIdx.x * blockDim.x + threadIdx.x;
    if (i < n) { g_cntA[i] = 0; g_cntB[i] = 0; }
}

// ---------------------------------------------------------------------------
// K2: bucket A by ROW.  a_idx[t]=row i, a_idx[nnz+t]=col k.
// ---------------------------------------------------------------------------
__global__ void build_a_kernel(const int* __restrict__ a_idx,
                               const float* __restrict__ a_val,
                               int nnz, int n) {
    int t = blockIdx.x * blockDim.x + threadIdx.x;
    if (t >= nnz) return;
    int i = a_idx[t];
    int k = a_idx[nnz + t];
    if ((unsigned)i >= (unsigned)n) return;
    int slot = atomicAdd(&g_cntA[i], 1);
    if (slot < CAP) {
        g_kA[i * CAP + slot] = k;
        g_vA[i * CAP + slot] = a_val[t];
    }
}

// ---------------------------------------------------------------------------
// K3: bucket B by ROW.  b_idx[t]=row k, b_idx[nnz+t]=col j.
// ---------------------------------------------------------------------------
__global__ void build_b_kernel(const int* __restrict__ b_idx,
                               const float* __restrict__ b_val,
                               int nnz, int n) {
    int t = blockIdx.x * blockDim.x + threadIdx.x;
    if (t >= nnz) return;
    int k = b_idx[t];
    int j = b_idx[nnz + t];
    if ((unsigned)k >= (unsigned)n) return;
    int slot = atomicAdd(&g_cntB[k], 1);
    if (slot < CAP) {
        g_cB[k * CAP + slot] = j;
        g_vB[k * CAP + slot] = b_val[t];
    }
}

// ---------------------------------------------------------------------------
// K4: one CTA per output row i. SMEM row accumulator + shared atomics, then
// coalesced float4 streaming write of the finished row.
// ---------------------------------------------------------------------------
#define ROW_THREADS 256

__global__ void __launch_bounds__(ROW_THREADS)
row_product_kernel(float* __restrict__ C, int n) {
    int i = blockIdx.x;

    __shared__ float acc[N_MAX];         // 16 KB

    int tid  = threadIdx.x;
    int lane = tid & 31;
    int warp = tid >> 5;                  // 0..7

    // zero accumulator (vectorized)
    float4* acc4 = reinterpret_cast<float4*>(acc);
    #pragma unroll
    for (int t = tid; t < N_MAX / 4; t += ROW_THREADS)
        acc4[t] = make_float4(0.f, 0.f, 0.f, 0.f);
    __syncthreads();

    int cA = min(g_cntA[i], CAP);

    // each warp takes A entries round-robin; lanes stride the B bucket
    for (int ia = warp; ia < cA; ia += ROW_THREADS / 32) {
        int   k  = g_kA[i * CAP + ia];
        float av = g_vA[i * CAP + ia];
        int   cB = min(g_cntB[k], CAP);
        const int*   cb = &g_cB[k * CAP];
        const float* vb = &g_vB[k * CAP];
        for (int jb = lane; jb < cB; jb += 32) {
            atomicAdd(&acc[cb[jb]], av * vb[jb]);
        }
    }
    __syncthreads();

    // stream out the finished row, fully coalesced
    float4* out4 = reinterpret_cast<float4*>(C + (long long)i * n);
    #pragma unroll
    for (int t = tid; t < N_MAX / 4; t += ROW_THREADS)
        out4[t] = acc4[t];
}

// ---------------------------------------------------------------------------
// Host launcher (graph-capturable: kernel launches only)
// ---------------------------------------------------------------------------
extern "C" void kernel_launch(void* const* d_in, const int* in_sizes, int n_in,
                              void* d_out, int out_size) {
    const int*   a_idx = (const int*)  d_in[0];   // [2, NNZA]
    const float* a_val = (const float*)d_in[1];   // [NNZA]
    const int*   b_idx = (const int*)  d_in[2];   // [2, NNZB]
    const float* b_val = (const float*)d_in[3];   // [NNZB]
    float*       C     = (float*)d_out;

    int nnzA = in_sizes[1];
    int nnzB = in_sizes[3];
    int N    = (int)(sqrt((double)out_size) + 0.5);   // 4096

    zero_counters<<<(N + 255) / 256, 256>>>(N);
    build_a_kernel<<<(nnzA + 255) / 256, 256>>>(a_idx, a_val, nnzA, N);
    build_b_kernel<<<(nnzB + 255) / 256, 256>>>(b_idx, b_val, nnzB, N);
    row_product_kernel<<<N, ROW_THREADS>>>(C, N);
}

// round 3
// speedup vs baseline: 1.3730x; 1.1076x over previous
#include <cuda_runtime.h>
#include <math.h>

// ---------------------------------------------------------------------------
// SpSpMM: C[n,n] = A @ B, COO inputs (duplicates sum), dense f32 output.
//
// Row formulation: C[i,:] = sum over A-entries (i,k,av) of av * B[k,:].
// Two launches only:
//   K1 fused_build : bucket A by row i and B by row k (packed int2 {idx,val})
//   K2 row_product : one CTA per row, SMEM accumulator + shared atomics,
//                    coalesced writeout; last CTA re-zeroes the counters so
//                    no separate zero pass is needed (module init covers the
//                    first call, each launch leaves counters zeroed).
// Product kernel sits on the ATOMS spread-addr floor (~2 cyc/lane).
// ---------------------------------------------------------------------------

#define N_MAX 4096
#define CAP   256      // per-bucket capacity (mean 32; overflow prob ~ 0)

__device__ int      g_cntA[N_MAX];          // entries of A in row i
__device__ int      g_cntB[N_MAX];          // entries of B in row k
__device__ int2     g_A[N_MAX * CAP];       // {col k, bits(val)} per A row
__device__ int2     g_B[N_MAX * CAP];       // {col j, bits(val)} per B row
__device__ unsigned g_done = 0;             // CTA completion counter

// ---------------------------------------------------------------------------
// K1: fused bucketing. Threads [0,nnzA) handle A, [nnzA, nnzA+nnzB) handle B.
//     idx layout [2, nnz]: idx[t]=row, idx[nnz+t]=col.
// ---------------------------------------------------------------------------
__global__ void fused_build_kernel(const int* __restrict__ a_idx,
                                   const float* __restrict__ a_val, int nnzA,
                                   const int* __restrict__ b_idx,
                                   const float* __restrict__ b_val, int nnzB,
                                   int n) {
    int t = blockIdx.x * blockDim.x + threadIdx.x;
    if (t < nnzA) {
        int i = a_idx[t];
        int k = a_idx[nnzA + t];
        if ((unsigned)i < (unsigned)n) {
            int slot = atomicAdd(&g_cntA[i], 1);
            if (slot < CAP)
                g_A[i * CAP + slot] = make_int2(k, __float_as_int(a_val[t]));
        }
    } else {
        int u = t - nnzA;
        if (u < nnzB) {
            int k = b_idx[u];
            int j = b_idx[nnzB + u];
            if ((unsigned)k < (unsigned)n) {
                int slot = atomicAdd(&g_cntB[k], 1);
                if (slot < CAP)
                    g_B[k * CAP + slot] = make_int2(j, __float_as_int(b_val[u]));
            }
        }
    }
}

// ---------------------------------------------------------------------------
// K2: one CTA per output row i.
// ---------------------------------------------------------------------------
#define ROW_THREADS 256

__global__ void __launch_bounds__(ROW_THREADS)
row_product_kernel(float* __restrict__ C, int n) {
    int i = blockIdx.x;

    __shared__ float acc[N_MAX];       // 16 KB row accumulator
    __shared__ int2  sA[CAP];          // staged A-row list
    __shared__ int   s_last;

    int tid  = threadIdx.x;
    int lane = tid & 31;
    int warp = tid >> 5;               // 0..7

    // zero accumulator (vectorized)
    float4* acc4 = reinterpret_cast<float4*>(acc);
    #pragma unroll
    for (int t = tid; t < N_MAX / 4; t += ROW_THREADS)
        acc4[t] = make_float4(0.f, 0.f, 0.f, 0.f);

    int cA = min(g_cntA[i], CAP);
    // stage A-row bucket cooperatively (coalesced LDG.64)
    if (tid < cA) sA[tid] = g_A[i * CAP + tid];
    __syncthreads();

    // each warp takes A entries round-robin; lanes stride the B bucket
    for (int ia = warp; ia < cA; ia += ROW_THREADS / 32) {
        int2  e  = sA[ia];
        int   k  = e.x;
        float av = __int_as_float(e.y);
        int   cB = min(g_cntB[k], CAP);
        const int2* __restrict__ Bk = g_B + k * CAP;
        for (int jb = lane; jb < cB; jb += 32) {
            int2 b = Bk[jb];
            atomicAdd(&acc[b.x], av * __int_as_float(b.y));
        }
    }
    __syncthreads();

    // stream out the finished row, fully coalesced
    float4* out4 = reinterpret_cast<float4*>(C + (long long)i * n);
    #pragma unroll
    for (int t = tid; t < N_MAX / 4; t += ROW_THREADS)
        out4[t] = acc4[t];

    // ---- counter reset by the last CTA to finish (replaces zero pass) ----
    if (tid == 0) {
        __threadfence();                               // reads above done
        unsigned prev = atomicAdd(&g_done, 1u);
        s_last = (prev == (unsigned)(gridDim.x - 1));
    }
    __syncthreads();
    if (s_last) {
        for (int t = tid; t < n; t += ROW_THREADS) {
            g_cntA[t] = 0;
            g_cntB[t] = 0;
        }
        if (tid == 0) g_done = 0;
    }
}

// ---------------------------------------------------------------------------
// Host launcher (graph-capturable: kernel launches only)
// ---------------------------------------------------------------------------
extern "C" void kernel_launch(void* const* d_in, const int* in_sizes, int n_in,
                              void* d_out, int out_size) {
    const int*   a_idx = (const int*)  d_in[0];   // [2, NNZA]
    const float* a_val = (const float*)d_in[1];   // [NNZA]
    const int*   b_idx = (const int*)  d_in[2];   // [2, NNZB]
    const float* b_val = (const float*)d_in[3];   // [NNZB]
    float*       C     = (float*)d_out;

    int nnzA = in_sizes[1];
    int nnzB = in_sizes[3];
    int N    = (int)(sqrt((double)out_size) + 0.5);   // 4096

    int total = nnzA + nnzB;
    fused_build_kernel<<<(total + 255) / 256, 256>>>(a_idx, a_val, nnzA,
                                                     b_idx, b_val, nnzB, N);
    row_product_kernel<<<N, ROW_THREADS>>>(C, N);
}